// round 8
// baseline (speedup 1.0000x reference)
#include <cuda_runtime.h>

#define NN 100000
#define NE 3200000
#define KF 1433
#define NH 16
#define NO 7

// ---------------- scratch (device globals; no allocation allowed) ----------
__device__ float g_deg_out[NN];               // becomes norm_src after norm_kernel
__device__ float g_deg_in[NN];                // becomes norm_dst after norm_kernel
__device__ __align__(16) float g_x1[NN * 16];   // RAW feat@W1 (unscaled)
__device__ __align__(16) float g_m1[NN * 16];
__device__ __align__(16) float g_x2[NN * 8];
__device__ __align__(16) float g_m2[NN * 8];
__device__ int g_src[NE];
__device__ int g_dst[NE];
__device__ int g_is64;
// W1 pre-split into tf32 hi/lo, fragment-paired:
// g_Wp[h][i][col] (i = s*4+tg, 736 padded) = float2(W[8s+tg][col], W[8s+tg+4][col])
__device__ __align__(16) float2 g_Wp[2 * 736 * 16];

// ---------------- PTX helpers ----------------------------------------------
__device__ __forceinline__ void red4(float* p, float4 v) {
    asm volatile("red.global.add.v4.f32 [%0], {%1, %2, %3, %4};"
                 :: "l"(p), "f"(v.x), "f"(v.y), "f"(v.z), "f"(v.w)
                 : "memory");
}
__device__ __forceinline__ unsigned to_tf32(float x) {
    unsigned r;
    asm("cvt.rna.tf32.f32 %0, %1;" : "=r"(r) : "f"(x));
    return r;
}
__device__ __forceinline__ void split_tf32(float x, unsigned& hi, unsigned& lo) {
    hi = to_tf32(x);
    lo = to_tf32(x - __uint_as_float(hi));
}
__device__ __forceinline__ void mma_tf32(float* c, const unsigned* a, const unsigned* b) {
    asm volatile("mma.sync.aligned.m16n8k8.row.col.f32.tf32.tf32.f32 "
                 "{%0,%1,%2,%3}, {%4,%5,%6,%7}, {%8,%9}, {%0,%1,%2,%3};"
                 : "+f"(c[0]), "+f"(c[1]), "+f"(c[2]), "+f"(c[3])
                 : "r"(a[0]), "r"(a[1]), "r"(a[2]), "r"(a[3]),
                   "r"(b[0]), "r"(b[1]));
}

// ---------------- edge dtype detect ----------------------------------------
__global__ void detect_kernel(const void* ei) {
    const int* w = (const int*)ei;
    int t = threadIdx.x;
    int v = w[2 * t + 1];
    unsigned b = __ballot_sync(0xffffffffu, v != 0);
    if (t == 0) g_is64 = (b == 0) ? 1 : 0;
}

// ---------------- fused convert + degree histogram (one edge pass) ---------
__global__ void convdeg_kernel(const void* ei) {
    int e = blockIdx.x * blockDim.x + threadIdx.x;
    if (e >= NE) return;
    int s, d;
    if (g_is64) {
        const long long* p = (const long long*)ei;
        s = (int)p[e];
        d = (int)p[NE + e];
    } else {
        const int* p = (const int*)ei;
        s = p[e];
        d = p[NE + e];
    }
    g_src[e] = s;
    g_dst[e] = d;
    atomicAdd(&g_deg_out[s], 1.0f);
    atomicAdd(&g_deg_in[d], 1.0f);
}

__global__ void norm_kernel() {
    int i = blockIdx.x * blockDim.x + threadIdx.x;
    if (i >= NN) return;
    g_deg_out[i] = rsqrtf(fmaxf(g_deg_out[i], 1.0f));
    g_deg_in[i]  = rsqrtf(fmaxf(g_deg_in[i], 1.0f));
}

// ---------------- W1 pre-split (tiny; runs before gemm1) -------------------
__global__ void wsplit_kernel(const float* __restrict__ W1) {
    int t = blockIdx.x * blockDim.x + threadIdx.x;
    if (t >= 1440 * 16) return;
    int k = t >> 4, col = t & 15;
    float wv = (k < KF) ? W1[k * NH + col] : 0.0f;
    unsigned hi, lo;
    split_tf32(wv, hi, lo);
    int s = k >> 3, tgk = k & 7;
    int i = s * 4 + (tgk & 3);
    int half = tgk >> 2;          // 0 -> .x (k=8s+tg), 1 -> .y (k=8s+tg+4)
    float* base = (float*)g_Wp;
    base[((0 * 736 + i) * 16 + col) * 2 + half] = __uint_as_float(hi);
    base[((1 * 736 + i) * 16 + col) * 2 + half] = __uint_as_float(lo);
}

// ---------------- GEMM1: x1_raw = feat @ W1  [100k x 16], 3xTF32 mma -------
// Block 256 thr = 8 warps; tile 128 nodes x 16 cols; k-chunk 32 (4 k8 steps).
// Warp w owns 16 rows [16w,16w+16) = one m16 tile, 2 n8 tiles.
// Alignment fix: row n base is (n&3)*4 mod 16 bytes; load a window shifted
// down by s_n=(n&3) floats -> every LDG is a 16B-aligned LDG.128 (9 quads
// cover [k0-s_n, k0-s_n+36) ⊃ [k0,k0+32)). Store shifted into smem pitch 44
// with 4-col left pad; mma fragment LDS on pitch 44 is bank-conflict-free.
// W hi/lo pre-split (g_Wp) -> B frags are plain LDS.64, no cvt in loop.
#define TPITCH 44
#define A_ST (128 * TPITCH)               // 5632 floats per stage
#define W_ST 512                          // float2 per stage (2h x 16i x 16col)
#define SMEM_BYTES (2 * A_ST * 4 + 2 * W_ST * 8)   // 45056 + 8192 = 53248

__global__ void __launch_bounds__(256, 4) gemm1_kernel(const float* __restrict__ feat) {
    extern __shared__ float sm[];
    float* As0 = sm;
    float* As1 = sm + A_ST;
    float2* Ws = (float2*)(sm + 2 * A_ST);   // [stage][flat 512]

    const int tid = threadIdx.x;
    const int node0 = blockIdx.x * 128;
    const int w = tid >> 5, lane = tid & 31;
    const int g = lane >> 2, tg = lane & 3;

    float acc[2][4];
#pragma unroll
    for (int nt = 0; nt < 2; nt++)
#pragma unroll
        for (int j = 0; j < 4; j++) acc[nt][j] = 0.0f;

    float4 rA[5];
    float2 rW[2];

    // ---- load stage cc into registers (5 aligned LDG.128 + 2 LDG.64) ----
#define LOAD_STAGE(cc)                                                            \
    {                                                                             \
        const int k0 = (cc) * 32;                                                 \
        _Pragma("unroll")                                                         \
        for (int i = 0; i < 5; i++) {                                             \
            float4 v = make_float4(0.f, 0.f, 0.f, 0.f);                           \
            int f = tid + 256 * i;                                                \
            if (f < 1152) {                                                       \
                int r = f / 9, j = f - r * 9;                                     \
                int n = node0 + r;                                                \
                if (n < NN) {                                                     \
                    int sn = n & 3;                                               \
                    int ke = k0 - sn + 4 * j;                                     \
                    long long gi = (long long)n * KF + ke;                        \
                    if (gi + 4 > (long long)NN * KF)                              \
                        gi = (long long)NN * KF - 4;   /* stays 16B-aligned */    \
                    v = *(const float4*)(feat + gi);                              \
                    if (ke + 0 >= KF) v.x = 0.f;                                  \
                    if (ke + 1 >= KF) v.y = 0.f;                                  \
                    if (ke + 2 >= KF) v.z = 0.f;                                  \
                    if (ke + 3 >= KF) v.w = 0.f;                                  \
                }                                                                 \
            }                                                                     \
            rA[i] = v;                                                            \
        }                                                                         \
        _Pragma("unroll")                                                         \
        for (int u = 0; u < 2; u++) {                                             \
            int f2 = tid + 256 * u;                                               \
            int h = f2 >> 8, i16 = (f2 >> 4) & 15, col = f2 & 15;                 \
            rW[u] = g_Wp[(h * 736 + (cc) * 16 + i16) * 16 + col];                 \
        }                                                                         \
    }

    // ---- store staged registers into smem stage b ----
#define STORE_STAGE(Ab, b)                                                        \
    {                                                                             \
        _Pragma("unroll")                                                         \
        for (int i = 0; i < 5; i++) {                                             \
            int f = tid + 256 * i;                                                \
            if (f < 1152) {                                                       \
                int r = f / 9, j = f - r * 9;                                     \
                int sn = (node0 + r) & 3;                                         \
                float* p = (Ab) + r * TPITCH + 4 * j + 4 - sn;                    \
                p[0] = rA[i].x; p[1] = rA[i].y; p[2] = rA[i].z; p[3] = rA[i].w;   \
            }                                                                     \
        }                                                                         \
        Ws[(b) * W_ST + tid] = rW[0];                                             \
        Ws[(b) * W_ST + tid + 256] = rW[1];                                       \
    }

    const int NCHUNK = (KF + 31) / 32;   // 45

    LOAD_STAGE(0);
    STORE_STAGE(As0, 0);
    __syncthreads();

    const int arow = (w * 16 + g) * TPITCH;

    for (int c = 0; c < NCHUNK; c++) {
        const int buf = c & 1;
        const bool more = (c + 1 < NCHUNK);
        if (more) LOAD_STAGE(c + 1);

        const float* A = buf ? As1 : As0;
        const float2* WsB = Ws + buf * W_ST;
#pragma unroll
        for (int sl = 0; sl < 4; sl++) {
            const int cb = arow + 4 + sl * 8 + tg;
            float a0 = A[cb];
            float a1 = A[cb + 8 * TPITCH];
            float a2 = A[cb + 4];
            float a3 = A[cb + 8 * TPITCH + 4];
            unsigned ahi[4], alo[4];
            split_tf32(a0, ahi[0], alo[0]);
            split_tf32(a1, ahi[1], alo[1]);
            split_tf32(a2, ahi[2], alo[2]);
            split_tf32(a3, ahi[3], alo[3]);
            const int wi = (sl * 4 + tg) * 16;
#pragma unroll
            for (int nt = 0; nt < 2; nt++) {
                const int col = nt * 8 + g;
                float2 bh = WsB[wi + col];           // h=0 slab
                float2 bl = WsB[256 + wi + col];     // h=1 slab
                unsigned bhi[2] = { __float_as_uint(bh.x), __float_as_uint(bh.y) };
                unsigned blo[2] = { __float_as_uint(bl.x), __float_as_uint(bl.y) };
                mma_tf32(acc[nt], ahi, bhi);
                mma_tf32(acc[nt], ahi, blo);
                mma_tf32(acc[nt], alo, bhi);
            }
        }
        __syncthreads();
        if (more) {
            STORE_STAGE(buf ? As0 : As1, buf ^ 1);
            __syncthreads();
        }
    }

    // epilogue: D rows g, g+8 of warp's m16 tile; cols 2tg(+1) + 8nt
    const int n0 = node0 + w * 16 + g;
    const int n1 = n0 + 8;
#pragma unroll
    for (int nt = 0; nt < 2; nt++) {
        const int col = nt * 8 + 2 * tg;
        if (n0 < NN)
            *(float2*)&g_x1[n0 * 16 + col] = make_float2(acc[nt][0], acc[nt][1]);
        if (n1 < NN)
            *(float2*)&g_x1[n1 * 16 + col] = make_float2(acc[nt][2], acc[nt][3]);
    }
#undef LOAD_STAGE
#undef STORE_STAGE
}

// ---------------- scatter layer 1: m1[dst] += ns[src]*x1_raw[src] ----------
__global__ void scatter1_kernel() {
    int e = blockIdx.x * blockDim.x + threadIdx.x;
    if (e >= NE) return;
    int s = g_src[e];
    int d = g_dst[e];
    float ns = g_deg_out[s];   // norm_src (L2-resident, 400KB)
    const float4* x = (const float4*)(g_x1 + s * 16);
    float* m = g_m1 + d * 16;
    float4 v0 = x[0], v1 = x[1], v2 = x[2], v3 = x[3];
    v0.x *= ns; v0.y *= ns; v0.z *= ns; v0.w *= ns;
    v1.x *= ns; v1.y *= ns; v1.z *= ns; v1.w *= ns;
    v2.x *= ns; v2.y *= ns; v2.z *= ns; v2.w *= ns;
    v3.x *= ns; v3.y *= ns; v3.z *= ns; v3.w *= ns;
    red4(m, v0);
    red4(m + 4, v1);
    red4(m + 8, v2);
    red4(m + 12, v3);
}

// ---------------- mid: h = relu(m1*nd + b1); x2 = (h*ns) @ W2 (pad to 8) ---
__global__ void mid_kernel(const float* __restrict__ b1, const float* __restrict__ W2) {
    int n = blockIdx.x * blockDim.x + threadIdx.x;
    if (n >= NN) return;
    float nd = g_deg_in[n];   // norm_dst
    float ns = g_deg_out[n];  // norm_src
    float h[16];
    const float4* mp = (const float4*)(g_m1 + n * 16);
#pragma unroll
    for (int q = 0; q < 4; q++) {
        float4 v = mp[q];
        h[4 * q + 0] = fmaxf(v.x * nd + __ldg(&b1[4 * q + 0]), 0.0f);
        h[4 * q + 1] = fmaxf(v.y * nd + __ldg(&b1[4 * q + 1]), 0.0f);
        h[4 * q + 2] = fmaxf(v.z * nd + __ldg(&b1[4 * q + 2]), 0.0f);
        h[4 * q + 3] = fmaxf(v.w * nd + __ldg(&b1[4 * q + 3]), 0.0f);
    }
    float o[8];
#pragma unroll
    for (int c = 0; c < NO; c++) {
        float s = 0.0f;
#pragma unroll
        for (int j = 0; j < 16; j++) s = fmaf(h[j], __ldg(&W2[j * NO + c]), s);
        o[c] = ns * s;
    }
    o[7] = 0.0f;
    float4* xp = (float4*)(g_x2 + n * 8);
    xp[0] = make_float4(o[0], o[1], o[2], o[3]);
    xp[1] = make_float4(o[4], o[5], o[6], o[7]);
}

// ---------------- scatter layer 2: m2[dst] += x2[src] (8 floats) -----------
__global__ void scatter2_kernel() {
    int e = blockIdx.x * blockDim.x + threadIdx.x;
    if (e >= NE) return;
    int s = g_src[e];
    int d = g_dst[e];
    const float4* x = (const float4*)(g_x2 + s * 8);
    float* m = g_m2 + d * 8;
    float4 v0 = x[0], v1 = x[1];
    red4(m, v0);
    red4(m + 4, v1);
}

// ---------------- output: out = m2*nd + b2 ---------------------------------
__global__ void out_kernel(const float* __restrict__ b2, float* __restrict__ out) {
    int i = blockIdx.x * blockDim.x + threadIdx.x;
    if (i >= NN * NO) return;
    int n = i / NO;
    int c = i - n * NO;
    out[i] = g_m2[n * 8 + c] * g_deg_in[n] + __ldg(&b2[c]);
}

// ---------------- launch ---------------------------------------------------
extern "C" void kernel_launch(void* const* d_in, const int* in_sizes, int n_in,
                              void* d_out, int out_size) {
    const float* feat = (const float*)d_in[0];
    const void* ei    = d_in[1];
    const float* W1   = (const float*)d_in[2];
    const float* b1   = (const float*)d_in[3];
    const float* W2   = (const float*)d_in[4];
    const float* b2   = (const float*)d_in[5];
    float* out        = (float*)d_out;

    static cudaStream_t s2 = 0;
    static cudaEvent_t evA = 0, evB = 0;
    if (!s2) {
        cudaStreamCreateWithFlags(&s2, cudaStreamNonBlocking);
        cudaEventCreateWithFlags(&evA, cudaEventDisableTiming);
        cudaEventCreateWithFlags(&evB, cudaEventDisableTiming);
        cudaFuncSetAttribute(gemm1_kernel,
                             cudaFuncAttributeMaxDynamicSharedMemorySize, SMEM_BYTES);
    }

    void *pdo, *pdi, *pm1, *pm2;
    cudaGetSymbolAddress(&pdo, g_deg_out);
    cudaGetSymbolAddress(&pdi, g_deg_in);
    cudaGetSymbolAddress(&pm1, g_m1);
    cudaGetSymbolAddress(&pm2, g_m2);
    cudaMemsetAsync(pdo, 0, (size_t)NN * sizeof(float));
    cudaMemsetAsync(pdi, 0, (size_t)NN * sizeof(float));
    cudaMemsetAsync(pm1, 0, (size_t)NN * 16 * sizeof(float));
    cudaMemsetAsync(pm2, 0, (size_t)NN * 8 * sizeof(float));

    const int TB = 256;
    const int EBLK = NE / TB;               // 12500 (exact)
    const int NBLK = (NN + TB - 1) / TB;    // 391
    const int GBLK = (NN + 127) / 128;      // 782

    // fork: edge chain on s2; W split + gemm1 on main stream
    cudaEventRecord(evA, 0);
    cudaStreamWaitEvent(s2, evA, 0);
    detect_kernel<<<1, 32, 0, s2>>>(ei);
    convdeg_kernel<<<EBLK, TB, 0, s2>>>(ei);
    norm_kernel<<<NBLK, TB, 0, s2>>>();
    cudaEventRecord(evB, s2);

    wsplit_kernel<<<(1440 * 16 + TB - 1) / TB, TB>>>(W1);
    gemm1_kernel<<<GBLK, TB, SMEM_BYTES>>>(feat);

    // join (scatter1 needs src/dst, norms, and x1)
    cudaStreamWaitEvent(0, evB, 0);
    scatter1_kernel<<<EBLK, TB>>>();
    mid_kernel<<<NBLK, TB>>>(b1, W2);
    scatter2_kernel<<<EBLK, TB>>>();
    out_kernel<<<(NN * NO + TB - 1) / TB, TB>>>(b2, out);
}

// round 9
// speedup vs baseline: 2.1200x; 2.1200x over previous
#include <cuda_runtime.h>

#define NN 100000
#define NE 3200000
#define KF 1433
#define NH 16
#define NO 7

// ---------------- scratch (device globals; no allocation allowed) ----------
__device__ float g_deg_out[NN];               // becomes norm_src after norm_kernel
__device__ float g_deg_in[NN];                // becomes norm_dst after norm_kernel
__device__ __align__(16) float g_x1[NN * 16];   // RAW feat@W1 (unscaled)
__device__ __align__(16) float g_m1[NN * 16];
__device__ __align__(16) float g_x2[NN * 8];
__device__ __align__(16) float g_m2[NN * 8];
__device__ int g_src[NE];
__device__ int g_dst[NE];
__device__ int g_is64;
// W1 pre-split into tf32 hi/lo, [k][col] layout, k padded to 1440 (45 chunks)
__device__ __align__(16) float g_Whi[1440 * 16];
__device__ __align__(16) float g_Wlo[1440 * 16];

// ---------------- PTX helpers ----------------------------------------------
__device__ __forceinline__ void red4(float* p, float4 v) {
    asm volatile("red.global.add.v4.f32 [%0], {%1, %2, %3, %4};"
                 :: "l"(p), "f"(v.x), "f"(v.y), "f"(v.z), "f"(v.w)
                 : "memory");
}
__device__ __forceinline__ unsigned to_tf32(float x) {
    unsigned r;
    asm("cvt.rna.tf32.f32 %0, %1;" : "=r"(r) : "f"(x));
    return r;
}
__device__ __forceinline__ void split_tf32(float x, unsigned& hi, unsigned& lo) {
    hi = to_tf32(x);
    lo = to_tf32(x - __uint_as_float(hi));
}
__device__ __forceinline__ void mma_tf32(float* c, const unsigned* a, const unsigned* b) {
    asm volatile("mma.sync.aligned.m16n8k8.row.col.f32.tf32.tf32.f32 "
                 "{%0,%1,%2,%3}, {%4,%5,%6,%7}, {%8,%9}, {%0,%1,%2,%3};"
                 : "+f"(c[0]), "+f"(c[1]), "+f"(c[2]), "+f"(c[3])
                 : "r"(a[0]), "r"(a[1]), "r"(a[2]), "r"(a[3]),
                   "r"(b[0]), "r"(b[1]));
}

// ---------------- edge dtype detect ----------------------------------------
// int64 edges: every odd 32-bit word (high half) is 0. int32 edges: odd words
// are random node ids in [0, 100000) — all-32-zero has probability ~1e-160.
__global__ void detect_kernel(const void* ei) {
    const int* w = (const int*)ei;
    int t = threadIdx.x;
    int v = w[2 * t + 1];
    unsigned b = __ballot_sync(0xffffffffu, v != 0);
    if (t == 0) g_is64 = (b == 0) ? 1 : 0;
}

// ---------------- fused convert + degree histogram (one edge pass) ---------
__global__ void convdeg_kernel(const void* ei) {
    int e = blockIdx.x * blockDim.x + threadIdx.x;
    if (e >= NE) return;
    int s, d;
    if (g_is64) {
        const long long* p = (const long long*)ei;
        s = (int)p[e];
        d = (int)p[NE + e];
    } else {
        const int* p = (const int*)ei;
        s = p[e];
        d = p[NE + e];
    }
    g_src[e] = s;
    g_dst[e] = d;
    atomicAdd(&g_deg_out[s], 1.0f);
    atomicAdd(&g_deg_in[d], 1.0f);
}

__global__ void norm_kernel() {
    int i = blockIdx.x * blockDim.x + threadIdx.x;
    if (i >= NN) return;
    g_deg_out[i] = rsqrtf(fmaxf(g_deg_out[i], 1.0f));
    g_deg_in[i]  = rsqrtf(fmaxf(g_deg_in[i], 1.0f));
}

// ---------------- W1 pre-split (tiny; runs before gemm1) -------------------
__global__ void wsplit_kernel(const float* __restrict__ W1) {
    int t = blockIdx.x * blockDim.x + threadIdx.x;
    if (t >= 1440 * 16) return;
    int k = t >> 4, col = t & 15;
    float wv = (k < KF) ? W1[k * NH + col] : 0.0f;
    unsigned hi, lo;
    split_tf32(wv, hi, lo);
    g_Whi[t] = __uint_as_float(hi);
    g_Wlo[t] = __uint_as_float(lo);
}

// ---------------- GEMM1: x1_raw = feat @ W1  [100k x 16], 3xTF32 mma -------
// Structure identical to the proven R7 kernel (256-node tile, 8 warps,
// pitch-36 A smem, 2-stage reg->smem pipeline, 12 mma per s-step) with two
// fixes:
//  (1) coalesced loads: warp w owns rows [32w,32w+32); each LDG.32 reads
//      one row x 32 consecutive floats (1-2 cache lines per instruction,
//      vs ~16 sectors before).
//  (2) W hi/lo pre-split in gmem (g_Whi/g_Wlo), staged to smem slabs; no
//      cvt/fsub for W in the inner loop.
#define APITCH 36
#define A_ST (256 * APITCH)              // 9216 floats per stage
#define W_ST 1024                        // [2 halves][32 k][16 col] floats
#define SMEM_BYTES ((2 * A_ST + 2 * W_ST) * 4)   // 81920 B

__global__ void __launch_bounds__(256, 2) gemm1_kernel(const float* __restrict__ feat) {
    extern __shared__ float sm[];
    float* As0 = sm;
    float* As1 = sm + A_ST;
    float* Ws0 = sm + 2 * A_ST;          // [2][32][16]
    float* Ws1 = Ws0 + W_ST;

    const int tid  = threadIdx.x;
    const int node0 = blockIdx.x * 256;
    const int w    = tid >> 5;
    const int lane = tid & 31;
    const int g    = lane >> 2;     // mma group id
    const int tg   = lane & 3;      // thread-in-group
    const int wb   = w * 32;        // warp's local node base

    float acc[2][2][4];
#pragma unroll
    for (int mt = 0; mt < 2; mt++)
#pragma unroll
        for (int nt = 0; nt < 2; nt++)
#pragma unroll
            for (int j = 0; j < 4; j++) acc[mt][nt][j] = 0.0f;

    float rA[32];
    float rW[4];

    // ---- load chunk cc into registers: 32 coalesced LDG.32 + 4 W LDG ----
#define LOAD_REGS(cc)                                                             \
    {                                                                             \
        const int k0 = (cc) * 32;                                                 \
        const int kk = k0 + lane;                                                 \
        const int kok = (kk < KF) ? 1 : 0;                                        \
        _Pragma("unroll")                                                         \
        for (int i = 0; i < 32; i++) {                                            \
            int n = node0 + wb + i;                                               \
            rA[i] = (n < NN && kok) ? feat[(size_t)n * KF + kk] : 0.0f;           \
        }                                                                         \
        rW[0] = g_Whi[(cc) * 512 + tid];                                          \
        rW[1] = (tid < 256) ? g_Whi[(cc) * 512 + 256 + tid] : 0.0f;               \
        rW[2] = g_Wlo[(cc) * 512 + tid];                                          \
        rW[3] = (tid < 256) ? g_Wlo[(cc) * 512 + 256 + tid] : 0.0f;               \
    }

    // ---- store staged registers into smem stage ----
#define STORE_STAGE(Ab, Wb)                                                       \
    {                                                                             \
        _Pragma("unroll")                                                         \
        for (int i = 0; i < 32; i++) (Ab)[(wb + i) * APITCH + lane] = rA[i];      \
        (Wb)[tid] = rW[0];                                                        \
        (Wb)[256 + tid] = rW[1];                                                  \
        (Wb)[512 + tid] = rW[2];                                                  \
        (Wb)[768 + tid] = rW[3];                                                  \
    }

    const int NCHUNK = (KF + 31) / 32;   // 45

    LOAD_REGS(0);
    STORE_STAGE(As0, Ws0);
    __syncthreads();

    for (int c = 0; c < NCHUNK; c++) {
        const int buf = c & 1;
        const bool more = (c + 1 < NCHUNK);
        if (more) LOAD_REGS(c + 1);

        const float* A  = buf ? As1 : As0;
        const float* WB = buf ? Ws1 : Ws0;
#pragma unroll
        for (int s = 0; s < 4; s++) {
            unsigned ahi[2][4], alo[2][4];
#pragma unroll
            for (int mt = 0; mt < 2; mt++) {
                int r0 = (wb + 16 * mt + g) * APITCH + s * 8 + tg;
                int r1 = r0 + 8 * APITCH;
                split_tf32(A[r0],     ahi[mt][0], alo[mt][0]);
                split_tf32(A[r1],     ahi[mt][1], alo[mt][1]);
                split_tf32(A[r0 + 4], ahi[mt][2], alo[mt][2]);
                split_tf32(A[r1 + 4], ahi[mt][3], alo[mt][3]);
            }
            unsigned bhi[2][2], blo[2][2];
#pragma unroll
            for (int nt = 0; nt < 2; nt++) {
                int b0 = (s * 8 + tg) * 16 + nt * 8 + g;
                bhi[nt][0] = __float_as_uint(WB[b0]);
                bhi[nt][1] = __float_as_uint(WB[b0 + 64]);        // k+4
                blo[nt][0] = __float_as_uint(WB[512 + b0]);
                blo[nt][1] = __float_as_uint(WB[512 + b0 + 64]);
            }
#pragma unroll
            for (int mt = 0; mt < 2; mt++)
#pragma unroll
                for (int nt = 0; nt < 2; nt++) {
                    mma_tf32(acc[mt][nt], ahi[mt], bhi[nt]);
                    mma_tf32(acc[mt][nt], ahi[mt], blo[nt]);
                    mma_tf32(acc[mt][nt], alo[mt], bhi[nt]);
                }
        }
        __syncthreads();
        if (more) {
            STORE_STAGE(buf ? As0 : As1, buf ? Ws0 : Ws1);
            __syncthreads();
        }
    }

    // epilogue: D[g+16mt(+8)][2tg(+1) + 8nt] per mma layout; store float2
#pragma unroll
    for (int mt = 0; mt < 2; mt++) {
        int n0 = node0 + wb + 16 * mt + g;
        int n1 = n0 + 8;
#pragma unroll
        for (int nt = 0; nt < 2; nt++) {
            int col = nt * 8 + 2 * tg;
            if (n0 < NN)
                *(float2*)&g_x1[n0 * 16 + col] = make_float2(acc[mt][nt][0], acc[mt][nt][1]);
            if (n1 < NN)
                *(float2*)&g_x1[n1 * 16 + col] = make_float2(acc[mt][nt][2], acc[mt][nt][3]);
        }
    }
#undef LOAD_REGS
#undef STORE_STAGE
}

// ---------------- scatter layer 1: m1[dst] += ns[src]*x1_raw[src] ----------
__global__ void scatter1_kernel() {
    int e = blockIdx.x * blockDim.x + threadIdx.x;
    if (e >= NE) return;
    int s = g_src[e];
    int d = g_dst[e];
    float ns = g_deg_out[s];   // norm_src (L2-resident, 400KB)
    const float4* x = (const float4*)(g_x1 + s * 16);
    float* m = g_m1 + d * 16;
    float4 v0 = x[0], v1 = x[1], v2 = x[2], v3 = x[3];
    v0.x *= ns; v0.y *= ns; v0.z *= ns; v0.w *= ns;
    v1.x *= ns; v1.y *= ns; v1.z *= ns; v1.w *= ns;
    v2.x *= ns; v2.y *= ns; v2.z *= ns; v2.w *= ns;
    v3.x *= ns; v3.y *= ns; v3.z *= ns; v3.w *= ns;
    red4(m, v0);
    red4(m + 4, v1);
    red4(m + 8, v2);
    red4(m + 12, v3);
}

// ---------------- mid: h = relu(m1*nd + b1); x2 = (h*ns) @ W2 (pad to 8) ---
__global__ void mid_kernel(const float* __restrict__ b1, const float* __restrict__ W2) {
    int n = blockIdx.x * blockDim.x + threadIdx.x;
    if (n >= NN) return;
    float nd = g_deg_in[n];   // norm_dst
    float ns = g_deg_out[n];  // norm_src
    float h[16];
    const float4* mp = (const float4*)(g_m1 + n * 16);
#pragma unroll
    for (int q = 0; q < 4; q++) {
        float4 v = mp[q];
        h[4 * q + 0] = fmaxf(v.x * nd + __ldg(&b1[4 * q + 0]), 0.0f);
        h[4 * q + 1] = fmaxf(v.y * nd + __ldg(&b1[4 * q + 1]), 0.0f);
        h[4 * q + 2] = fmaxf(v.z * nd + __ldg(&b1[4 * q + 2]), 0.0f);
        h[4 * q + 3] = fmaxf(v.w * nd + __ldg(&b1[4 * q + 3]), 0.0f);
    }
    float o[8];
#pragma unroll
    for (int c = 0; c < NO; c++) {
        float s = 0.0f;
#pragma unroll
        for (int j = 0; j < 16; j++) s = fmaf(h[j], __ldg(&W2[j * NO + c]), s);
        o[c] = ns * s;
    }
    o[7] = 0.0f;
    float4* xp = (float4*)(g_x2 + n * 8);
    xp[0] = make_float4(o[0], o[1], o[2], o[3]);
    xp[1] = make_float4(o[4], o[5], o[6], o[7]);
}

// ---------------- scatter layer 2: m2[dst] += x2[src] (8 floats) -----------
__global__ void scatter2_kernel() {
    int e = blockIdx.x * blockDim.x + threadIdx.x;
    if (e >= NE) return;
    int s = g_src[e];
    int d = g_dst[e];
    const float4* x = (const float4*)(g_x2 + s * 8);
    float* m = g_m2 + d * 8;
    float4 v0 = x[0], v1 = x[1];
    red4(m, v0);
    red4(m + 4, v1);
}

// ---------------- output: out = m2*nd + b2 ---------------------------------
__global__ void out_kernel(const float* __restrict__ b2, float* __restrict__ out) {
    int i = blockIdx.x * blockDim.x + threadIdx.x;
    if (i >= NN * NO) return;
    int n = i / NO;
    int c = i - n * NO;
    out[i] = g_m2[n * 8 + c] * g_deg_in[n] + __ldg(&b2[c]);
}

// ---------------- launch ---------------------------------------------------
extern "C" void kernel_launch(void* const* d_in, const int* in_sizes, int n_in,
                              void* d_out, int out_size) {
    const float* feat = (const float*)d_in[0];
    const void* ei    = d_in[1];
    const float* W1   = (const float*)d_in[2];
    const float* b1   = (const float*)d_in[3];
    const float* W2   = (const float*)d_in[4];
    const float* b2   = (const float*)d_in[5];
    float* out        = (float*)d_out;

    // one-time host-side setup (first call is the non-captured correctness
    // run; no device memory is allocated here)
    static cudaStream_t s2 = 0;
    static cudaEvent_t evA = 0, evB = 0;
    if (!s2) {
        cudaStreamCreateWithFlags(&s2, cudaStreamNonBlocking);
        cudaEventCreateWithFlags(&evA, cudaEventDisableTiming);
        cudaEventCreateWithFlags(&evB, cudaEventDisableTiming);
        cudaFuncSetAttribute(gemm1_kernel,
                             cudaFuncAttributeMaxDynamicSharedMemorySize, SMEM_BYTES);
    }

    void *pdo, *pdi, *pm1, *pm2;
    cudaGetSymbolAddress(&pdo, g_deg_out);
    cudaGetSymbolAddress(&pdi, g_deg_in);
    cudaGetSymbolAddress(&pm1, g_m1);
    cudaGetSymbolAddress(&pm2, g_m2);
    cudaMemsetAsync(pdo, 0, (size_t)NN * sizeof(float));
    cudaMemsetAsync(pdi, 0, (size_t)NN * sizeof(float));
    cudaMemsetAsync(pm1, 0, (size_t)NN * 16 * sizeof(float));
    cudaMemsetAsync(pm2, 0, (size_t)NN * 8 * sizeof(float));

    const int TB = 256;
    const int EBLK = NE / TB;               // 12500 (exact)
    const int NBLK = (NN + TB - 1) / TB;    // 391

    // fork: edge chain on s2; W split + gemm1 on main stream
    cudaEventRecord(evA, 0);
    cudaStreamWaitEvent(s2, evA, 0);
    detect_kernel<<<1, 32, 0, s2>>>(ei);
    convdeg_kernel<<<EBLK, TB, 0, s2>>>(ei);
    norm_kernel<<<NBLK, TB, 0, s2>>>();
    cudaEventRecord(evB, s2);

    wsplit_kernel<<<(1440 * 16 + TB - 1) / TB, TB>>>(W1);
    gemm1_kernel<<<NBLK, TB, SMEM_BYTES>>>(feat);

    // join (scatter1 needs src/dst, norms, and x1)
    cudaStreamWaitEvent(0, evB, 0);
    scatter1_kernel<<<EBLK, TB>>>();
    mid_kernel<<<NBLK, TB>>>(b1, W2);
    scatter2_kernel<<<EBLK, TB>>>();
    out_kernel<<<(NN * NO + TB - 1) / TB, TB>>>(b2, out);
}